// round 2
// baseline (speedup 1.0000x reference)
#include <cuda_runtime.h>
#include <cuda_bf16.h>

// ---------------------------------------------------------------------------
// Ptychography forward model (sm_103a).
// Per (b,m) 256x256 tile: fft2 -> xphase -> ifft2 -> [xpatch_s -> fft2 -> xTF
// -> ifft2]x3 -> xpatch_3 -> fft2 -> |.|^2 mode-sum (ortho, fftshifted).
// Implemented as 10 fused 1-D passes with transpose-on-write.
// FFT-256 = 16x16 four-step: register FFT-16, half-warp smem exchange,
// register FFT-16. 16 threads per line, 16 lines (256 threads) per CTA.
// ---------------------------------------------------------------------------

// ---- static device scratch (no allocations allowed) ----
__device__ float2 g_g[39 * 65536];        // probe tiles after first fft2 half / full
__device__ float2 g_psiA[256 * 65536];    // ping (128 MB)
__device__ float2 g_psiB[256 * 65536];    // pong (128 MB)
__device__ float2 g_tf[65536];            // angular-spectrum transfer function
__device__ int2   g_ipos[32];             // rounded positions (iy, ix)
__device__ float2 g_frac[32];             // fractional shifts (fy, fx)
__device__ float  g_w[32][4];             // OPR weights per batch item

// ---- complex helpers ----
__device__ __forceinline__ float2 cmul(float2 a, float2 b) {
    return make_float2(fmaf(a.x, b.x, -a.y * b.y), fmaf(a.x, b.y, a.y * b.x));
}

template<bool INV>
__device__ __forceinline__ void btf4(float2& a, float2& b, float2& c, float2& d) {
    float2 t0 = make_float2(a.x + c.x, a.y + c.y);
    float2 t1 = make_float2(a.x - c.x, a.y - c.y);
    float2 t2 = make_float2(b.x + d.x, b.y + d.y);
    float2 t3 = make_float2(b.x - d.x, b.y - d.y);
    a = make_float2(t0.x + t2.x, t0.y + t2.y);
    c = make_float2(t0.x - t2.x, t0.y - t2.y);
    if (!INV) {
        b = make_float2(t1.x + t3.y, t1.y - t3.x);   // t1 - i*t3
        d = make_float2(t1.x - t3.y, t1.y + t3.x);   // t1 + i*t3
    } else {
        b = make_float2(t1.x - t3.y, t1.y + t3.x);
        d = make_float2(t1.x + t3.y, t1.y - t3.x);
    }
}

// e^{-2 pi i m/16} (forward); conjugated for inverse. m in [0,9].
__device__ __forceinline__ float2 twv16(int m, bool inv) {
    const float C[10] = { 1.f, 0.92387953f, 0.70710678f, 0.38268343f, 0.f,
                         -0.38268343f, -0.70710678f, -0.92387953f, -1.f, -0.92387953f };
    const float S[10] = { 0.f, -0.38268343f, -0.70710678f, -0.92387953f, -1.f,
                         -0.92387953f, -0.70710678f, -0.38268343f, 0.f, 0.38268343f };
    return make_float2(C[m], inv ? -S[m] : S[m]);
}

// 16-point DFT in registers, natural order in/out.
template<bool INV>
__device__ __forceinline__ void fft16(float2* v) {
    float2 t[16];
#pragma unroll
    for (int a = 0; a < 4; a++) {
        float2 x0 = v[a], x1 = v[a + 4], x2 = v[a + 8], x3 = v[a + 12];
        btf4<INV>(x0, x1, x2, x3);
        t[4 * a + 0] = x0; t[4 * a + 1] = x1; t[4 * a + 2] = x2; t[4 * a + 3] = x3;
    }
#pragma unroll
    for (int c = 0; c < 4; c++) {
        float2 x0 = t[c], x1 = t[c + 4], x2 = t[c + 8], x3 = t[c + 12];
        if (c) {
            x1 = cmul(x1, twv16(c, INV));
            x2 = cmul(x2, twv16(2 * c, INV));
            x3 = cmul(x3, twv16(3 * c, INV));
        }
        btf4<INV>(x0, x1, x2, x3);
        v[c] = x0; v[c + 4] = x1; v[c + 8] = x2; v[c + 12] = x3;
    }
}

// 256-pt transform. Thread s (0..15) of a line holds element (s + 16*r) in
// v[r] on entry and on exit. xch = 256-float2 per-line smem region.
// INV folds the 1/256 backward-norm scale.
template<bool INV>
__device__ __forceinline__ void transform256(float2* v, float2* xch,
                                             const float2* tw, int s) {
    if (INV) {
#pragma unroll
        for (int r = 0; r < 16; r++) { v[r].x *= (1.0f / 256.0f); v[r].y *= (1.0f / 256.0f); }
    }
    fft16<INV>(v);
#pragma unroll
    for (int k2 = 1; k2 < 16; k2++) {               // cross twiddle W256^{s*k2}
        float2 w = tw[(s * k2) & 255];
        if (INV) w.y = -w.y;
        v[k2] = cmul(v[k2], w);
    }
    __syncwarp();
#pragma unroll
    for (int k2 = 0; k2 < 16; k2++) xch[s * 16 + ((k2 + s) & 15)] = v[k2];
    __syncwarp();
#pragma unroll
    for (int a = 0; a < 16; a++) v[a] = xch[a * 16 + ((s + a) & 15)];
    fft16<INV>(v);
}

__device__ __forceinline__ void init_tw(float2* tw, int tid) {
    if (tid < 256) {
        float sv, cv;
        sincospif(-(float)tid / 128.0f, &sv, &cv);   // e^{-2 pi i tid/256}
        tw[tid] = make_float2(cv, sv);
    }
}

// Transposed store of a CTA's 16 rows x 256 elements via smem staging.
// gout[e*256 + row0 + line] = element e of row (row0+line). Coalesced 128B.
__device__ __forceinline__ void store_transposed(const float2* v, float2* buf,
                                                 float2* gout, int row0,
                                                 int line, int s, int tid) {
    __syncthreads();
#pragma unroll
    for (int r = 0; r < 16; r++) buf[(s + 16 * r) * 17 + line] = v[r];
    __syncthreads();
    int l2 = tid & 15;
    int e0 = tid >> 4;
#pragma unroll
    for (int c = 0; c < 16; c++) {
        int e = c * 16 + e0;
        gout[e * 256 + row0 + l2] = buf[e * 17 + l2];
    }
}

// ---------------------------------------------------------------------------
// Setup kernels
// ---------------------------------------------------------------------------
__global__ void __launch_bounds__(256) kSetupPos(const float* positions,
                                                 const int* indices,
                                                 const float* opr) {
    int b = threadIdx.x;
    if (b < 32) {
        int idx = indices[b];
        float py = positions[idx * 2 + 0], px = positions[idx * 2 + 1];
        float ry = rintf(py), rx = rintf(px);       // round-half-even == jnp.round
        int iy = (int)ry, ix = (int)rx;
        iy = min(max(iy, 0), 768); ix = min(max(ix, 0), 768);  // dynamic_slice clamp
        g_ipos[b] = make_int2(iy, ix);
        g_frac[b] = make_float2(py - ry, px - rx);
        for (int k = 0; k < 4; k++) g_w[b][k] = opr[idx * 4 + k];
    }
}

__global__ void __launch_bounds__(256) kSetupTF() {
    int idx = blockIdx.x * 256 + threadIdx.x;
    int i = idx >> 8, j = idx & 255;
    // fp64 to match numpy (phase ~1e5 rad needs double range reduction)
    double fy = (double)((i < 128) ? i : i - 256) / (256.0 * 1.0e-8);
    double fx = (double)((j < 128) ? j : j - 256) / (256.0 * 1.0e-8);
    const double lam = 1.24e-10;
    double ax = lam * fx, ay = lam * fy;
    double arg = 1.0 - ax * ax - ay * ay;
    float2 tf = make_float2(0.f, 0.f);
    if (arg > 0.0) {
        double kz = (6.283185307179586 / lam) * sqrt(arg);
        double ph = 2.0e-6 * kz;
        tf = make_float2((float)cos(ph), (float)sin(ph));
    }
    g_tf[idx] = tf;
}

// ---------------------------------------------------------------------------
// P0: build 39 unique probe tiles (32 OPR combos + 7 shared modes),
//     FFT along x, store transposed [kx][y] into g_g.
// ---------------------------------------------------------------------------
__global__ void __launch_bounds__(256) kP0(const float* probe) {
    __shared__ float2 buf[256 * 17];
    __shared__ float2 tw[256];
    int tid = threadIdx.x;
    init_tw(tw, tid);
    __syncthreads();
    int u = blockIdx.y, row0 = blockIdx.x * 16;
    int line = tid >> 4, s = tid & 15;
    int y = row0 + line;
    const float2* p = (const float2*)probe;         // (K=4, M=8, 256, 256) complex
    float2 v[16];
    if (u < 32) {                                   // p0[b] = sum_k w[b,k] probe[k,0]
        float w0 = g_w[u][0], w1 = g_w[u][1], w2 = g_w[u][2], w3 = g_w[u][3];
        const float2* p0 = p + y * 256;
        const float2* p1 = p + 524288 + y * 256;
        const float2* p2 = p + 1048576 + y * 256;
        const float2* p3 = p + 1572864 + y * 256;
#pragma unroll
        for (int r = 0; r < 16; r++) {
            int x = s + 16 * r;
            float2 a = p0[x], b = p1[x], c = p2[x], d = p3[x];
            v[r] = make_float2(w0 * a.x + w1 * b.x + w2 * c.x + w3 * d.x,
                               w0 * a.y + w1 * b.y + w2 * c.y + w3 * d.y);
        }
    } else {                                        // probe[0, m] shared across b
        int m = u - 31;
        const float2* q = p + m * 65536 + y * 256;
#pragma unroll
        for (int r = 0; r < 16; r++) v[r] = q[s + 16 * r];
    }
    transform256<false>(v, buf + line * 256, tw, s);
    store_transposed(v, buf, g_g + u * 65536, row0, line, s, tid);
}

// ---------------------------------------------------------------------------
// P1: per (b,m): FFT along y -> [kx][ky], multiply subpixel phase ramp
//     (separable recurrence), IFFT along ky, store transposed [y][kx] -> psiA.
// ---------------------------------------------------------------------------
__global__ void __launch_bounds__(256) kP1() {
    __shared__ float2 buf[256 * 17];
    __shared__ float2 tw[256];
    __shared__ float2 phb[16], phx[16], phc[2];
    int tid = threadIdx.x;
    int t = blockIdx.y, row0 = blockIdx.x * 16;
    int b = t >> 3, m = t & 7;
    init_tw(tw, tid);
    float2 fr = g_frac[b];                          // (frac_y, frac_x)
    if (tid < 16) {                                 // e^{-2pi i fy*s/256}
        float sv, cv; sincospif(-fr.x * (float)tid / 128.0f, &sv, &cv);
        phb[tid] = make_float2(cv, sv);
    } else if (tid < 32) {                          // e^{-2pi i fx*f(kx)} per line
        int l = tid - 16, kx = row0 + l;
        float fk = (float)((kx < 128) ? kx : kx - 256) * (1.0f / 256.0f);
        float sv, cv; sincospif(-2.0f * fr.y * fk, &sv, &cv);
        phx[l] = make_float2(cv, sv);
    } else if (tid == 32) {                         // step e^{-2pi i fy/16}
        float sv, cv; sincospif(-fr.x / 8.0f, &sv, &cv);
        phc[0] = make_float2(cv, sv);
    } else if (tid == 33) {                         // wrap corr e^{+2pi i fy}
        float sv, cv; sincospif(2.0f * fr.x, &sv, &cv);
        phc[1] = make_float2(cv, sv);
    }
    __syncthreads();
    int line = tid >> 4, s = tid & 15;
    int kx = row0 + line;
    int u = (m == 0) ? b : 31 + m;
    const float2* src = g_g + u * 65536 + kx * 256;
    float2 v[16];
#pragma unroll
    for (int r = 0; r < 16; r++) v[r] = src[s + 16 * r];
    transform256<false>(v, buf + line * 256, tw, s);
    float2 step = phc[0], corr = phc[1];
    float2 cur = cmul(phx[line], phb[s]);
#pragma unroll
    for (int r = 0; r < 16; r++) {                  // ky = s + 16r
        if (r == 8) cur = cmul(cur, corr);          // ky >= 128: f = (ky-256)/256
        v[r] = cmul(v[r], cur);
        cur = cmul(cur, step);
    }
    transform256<true>(v, buf + line * 256, tw, s);
    store_transposed(v, buf, g_psiA + t * 65536, row0, line, s, tid);
}

// ---------------------------------------------------------------------------
// kMod: IFFT along kx -> real space, multiply object patch (slice), FFT along
//       x, store transposed [kx][y].  (P2 / P4 / P6 / P8)
// ---------------------------------------------------------------------------
__global__ void __launch_bounds__(256) kMod(const float* object, int slice, int srcA) {
    __shared__ float2 buf[256 * 17];
    __shared__ float2 tw[256];
    int tid = threadIdx.x;
    init_tw(tw, tid);
    __syncthreads();
    const float2* sbuf = srcA ? g_psiA : g_psiB;
    float2* dbuf = srcA ? g_psiB : g_psiA;
    int t = blockIdx.y, row0 = blockIdx.x * 16;
    int b = t >> 3;
    int line = tid >> 4, s = tid & 15;
    int y = row0 + line;
    const float2* sp = sbuf + t * 65536 + y * 256;
    float2 v[16];
#pragma unroll
    for (int r = 0; r < 16; r++) v[r] = sp[s + 16 * r];
    transform256<true>(v, buf + line * 256, tw, s);
    int2 ip = g_ipos[b];
    const float2* op = (const float2*)object + slice * 1048576
                     + (ip.x + y) * 1024 + ip.y;
#pragma unroll
    for (int r = 0; r < 16; r++) v[r] = cmul(v[r], op[s + 16 * r]);
    transform256<false>(v, buf + line * 256, tw, s);
    store_transposed(v, buf, dbuf + t * 65536, row0, line, s, tid);
}

// ---------------------------------------------------------------------------
// kProp: FFT along y -> [kx][ky], multiply TF (symmetric: indexed [kx][ky]
//        for coalescing), IFFT along ky, store transposed [y][kx]. (P3/P5/P7)
// ---------------------------------------------------------------------------
__global__ void __launch_bounds__(256) kProp(int srcA) {
    __shared__ float2 buf[256 * 17];
    __shared__ float2 tw[256];
    int tid = threadIdx.x;
    init_tw(tw, tid);
    __syncthreads();
    const float2* sbuf = srcA ? g_psiA : g_psiB;
    float2* dbuf = srcA ? g_psiB : g_psiA;
    int t = blockIdx.y, row0 = blockIdx.x * 16;
    int line = tid >> 4, s = tid & 15;
    int kx = row0 + line;
    const float2* sp = sbuf + t * 65536 + kx * 256;
    float2 v[16];
#pragma unroll
    for (int r = 0; r < 16; r++) v[r] = sp[s + 16 * r];
    transform256<false>(v, buf + line * 256, tw, s);
    const float2* tfp = g_tf + kx * 256;            // TF is symmetric in (ky,kx)
#pragma unroll
    for (int r = 0; r < 16; r++) v[r] = cmul(v[r], tfp[s + 16 * r]);
    transform256<true>(v, buf + line * 256, tw, s);
    store_transposed(v, buf, dbuf + t * 65536, row0, line, s, tid);
}

// ---------------------------------------------------------------------------
// P9: final FFT along y, |.|^2 accumulated over 8 modes, ortho 1/65536,
//     fftshift via output remap, coalesced stores via smem transpose.
// ---------------------------------------------------------------------------
__global__ void __launch_bounds__(256) kFinal(float* out) {
    __shared__ float2 buf[256 * 17];
    __shared__ float2 tw[256];
    int tid = threadIdx.x;
    init_tw(tw, tid);
    __syncthreads();
    int bb = blockIdx.y, row0 = blockIdx.x * 16;
    int line = tid >> 4, s = tid & 15;
    int kx = row0 + line;
    float acc[16];
#pragma unroll
    for (int r = 0; r < 16; r++) acc[r] = 0.f;
    for (int m = 0; m < 8; m++) {
        const float2* sp = g_psiB + (bb * 8 + m) * 65536 + kx * 256;
        float2 v[16];
#pragma unroll
        for (int r = 0; r < 16; r++) v[r] = sp[s + 16 * r];
        transform256<false>(v, buf + line * 256, tw, s);
#pragma unroll
        for (int r = 0; r < 16; r++)
            acc[r] = fmaf(v[r].x, v[r].x, fmaf(v[r].y, v[r].y, acc[r]));
    }
    float* sf = (float*)buf;
    __syncthreads();
#pragma unroll
    for (int r = 0; r < 16; r++) {
        int ky = s + 16 * r;
        int yo = (ky + 128) & 255;                  // fftshift rows
        sf[yo * 17 + line] = acc[r] * (1.0f / 65536.0f);  // ortho norm
    }
    __syncthreads();
    int xb0 = (row0 + 128) & 255;                   // fftshift cols (blockwise)
    int l2 = tid & 15, e0 = tid >> 4;
#pragma unroll
    for (int c = 0; c < 16; c++) {
        int yy = c * 16 + e0;
        out[bb * 65536 + yy * 256 + xb0 + l2] = sf[yy * 17 + l2];
    }
}

// ---------------------------------------------------------------------------
extern "C" void kernel_launch(void* const* d_in, const int* in_sizes, int n_in,
                              void* d_out, int out_size) {
    // identify inputs by element count (robust to metadata ordering)
    const float* object = nullptr;    // (4,1024,1024,2)  -> 8388608
    const float* probe = nullptr;     // (4,8,256,256,2)  -> 4194304
    const float* opr = nullptr;       // (512,4)          -> 2048
    const float* positions = nullptr; // (512,2)          -> 1024
    const int*   indices = nullptr;   // (32,)            -> 32
    for (int i = 0; i < n_in; i++) {
        switch (in_sizes[i]) {
            case 8388608: object    = (const float*)d_in[i]; break;
            case 4194304: probe     = (const float*)d_in[i]; break;
            case 2048:    opr       = (const float*)d_in[i]; break;
            case 1024:    positions = (const float*)d_in[i]; break;
            case 32:      indices   = (const int*)d_in[i];   break;
        }
    }
    float* out = (float*)d_out;

    kSetupPos<<<1, 32>>>(positions, indices, opr);
    kSetupTF<<<256, 256>>>();
    kP0<<<dim3(16, 39), 256>>>(probe);
    kP1<<<dim3(16, 256), 256>>>();                  // -> psiA [y][kx]
    kMod<<<dim3(16, 256), 256>>>(object, 0, 1);     // A -> B  [kx][y]
    kProp<<<dim3(16, 256), 256>>>(0);               // B -> A  [y][kx]
    kMod<<<dim3(16, 256), 256>>>(object, 1, 1);     // A -> B
    kProp<<<dim3(16, 256), 256>>>(0);               // B -> A
    kMod<<<dim3(16, 256), 256>>>(object, 2, 1);     // A -> B
    kProp<<<dim3(16, 256), 256>>>(0);               // B -> A
    kMod<<<dim3(16, 256), 256>>>(object, 3, 1);     // A -> B (incl. final fft-x)
    kFinal<<<dim3(16, 32), 256>>>(out);             // B -> intensities
}